// round 16
// baseline (speedup 1.0000x reference)
#include <cuda_runtime.h>
#include <cstdint>

// Problem constants (fixed shapes per reference setup_inputs)
constexpr int D  = 64;    // feature dim
constexpr int T  = 200;   // sequence length
constexpr int H0 = 80;    // hidden 0
constexpr int H1 = 40;    // hidden 1

constexpr float NEG_INF_F = -4294967295.0f;

// Shared-memory layout (in floats)
constexpr int KSTR  = 65;   // K tile row stride (odd -> conflict-free column reads)
constexpr int MSTR  = 80;   // M matrix row stride (16B-aligned rows for LDS.128)
constexpr int H0STR = 81;   // H0 tile row stride

constexpr int OFF_Q   = 0;
constexpr int OFF_M   = 64;                       // 64 x 80
constexpr int OFF_B0  = OFF_M  + D * MSTR;        // 5184
constexpr int OFF_W1  = OFF_B0 + H0;              // 5264 (80x40, rows 16B aligned)
constexpr int OFF_B1  = OFF_W1 + H0 * H1;         // 8464
constexpr int OFF_A0  = OFF_B1 + H1;              // 8504
constexpr int OFF_A1  = OFF_A0 + H0;              // 8584
constexpr int OFF_WO  = OFF_A1 + H1;              // 8624
constexpr int OFF_BO  = OFF_WO + H1;              // 8664
constexpr int OFF_RED = 8668;                     // 8 floats (warp partials)
constexpr int OFF_LOG = OFF_RED + 8;              // 8676, 200 floats
constexpr int OFF_K   = 8880;                     // 200 x 65
constexpr int OFF_H0V = OFF_K + T * KSTR;         // 21880, 200 x 81
constexpr int SMEM_FLOATS = OFF_H0V + T * H0STR;  // 38080 floats = 152320 B

// ---- packed f32x2 helpers (FFMA2 path on sm_103a) ----
__device__ __forceinline__ unsigned long long pk2(float lo, float hi) {
    unsigned long long r;
    asm("mov.b64 %0, {%1,%2};" : "=l"(r) : "f"(lo), "f"(hi));
    return r;
}
__device__ __forceinline__ void upk2(unsigned long long v, float& a, float& b) {
    asm("mov.b64 {%0,%1}, %2;" : "=f"(a), "=f"(b) : "l"(v));
}
__device__ __forceinline__ void fma2(unsigned long long& d, unsigned long long a, unsigned long long b) {
    asm("fma.rn.f32x2 %0, %1, %2, %0;" : "+l"(d) : "l"(a), "l"(b));
}

__global__ void __launch_bounds__(256, 1)
attn_din_kernel(const float* __restrict__ q,  const float* __restrict__ k,
                const float* __restrict__ v,  const float* __restrict__ W0,
                const float* __restrict__ b0, const float* __restrict__ a0,
                const float* __restrict__ W1, const float* __restrict__ b1,
                const float* __restrict__ a1, const float* __restrict__ Wo,
                const float* __restrict__ bo, const int* __restrict__ mask,
                float* __restrict__ out)
{
    extern __shared__ float sh[];
    const int tid = threadIdx.x;
    const int b   = blockIdx.x;

    // ---------------- Phase A: stage q + small params, init logits ----------------
    if (tid < D)  sh[OFF_Q + tid] = q[(size_t)b * D + tid];
    for (int i = tid; i < H0 * H1; i += 256) sh[OFF_W1 + i] = W1[i];
    if (tid < H1) { sh[OFF_B1 + tid] = b1[tid]; sh[OFF_A1 + tid] = a1[tid]; sh[OFF_WO + tid] = Wo[tid]; }
    if (tid < H0) sh[OFF_A0 + tid] = a0[tid];
    if (tid == 0) sh[OFF_BO] = bo[0];
    if (tid < T)  sh[OFF_LOG + tid] = 0.0f;
    __syncthreads();  // sQ ready

    // ---------------- Phase B: fold q into layer-0: M_b and bias_b; stage K tile ----------------
    // M[d][h] = W0[64+d][h] - W0[128+d][h] + q[d] * W0[192+d][h]
    for (int e = tid; e < D * H0; e += 256) {
        int d = e / H0, h = e - d * H0;
        sh[OFF_M + d * MSTR + h] =
            W0[(64 + d) * H0 + h] - W0[(128 + d) * H0 + h] + sh[OFF_Q + d] * W0[(192 + d) * H0 + h];
    }
    // bias0[h] = b0[h] + sum_d q[d]*(W0[d][h] + W0[128+d][h])
    if (tid < H0) {
        float s = b0[tid];
        #pragma unroll 4
        for (int d = 0; d < D; ++d)
            s += sh[OFF_Q + d] * (W0[d * H0 + tid] + W0[(128 + d) * H0 + tid]);
        sh[OFF_B0 + tid] = s;
    }
    // K tile: [t][d] with stride KSTR
    {
        const float4* kg = (const float4*)(k + (size_t)b * T * D);
        for (int i = tid; i < T * D / 4; i += 256) {
            int t = i / (D / 4), c = i - t * (D / 4);
            float4 vv = kg[i];
            float* dst = &sh[OFF_K + t * KSTR + c * 4];
            dst[0] = vv.x; dst[1] = vv.y; dst[2] = vv.z; dst[3] = vv.w;
        }
    }
    __syncthreads();

    // ---------------- GEMM1: H0[200][80] = K[200][64] @ M[64][80], fused bias+PReLU --------------
    // 250 tiles of 8 pos x 8 h; output-feature pairs packed in f32x2 (weights via LDS.128 pairs)
    if (tid < 250) {
        const int hg = tid % 10, pg = tid / 10;
        const int p0 = pg * 8, hb = hg * 8;
        unsigned long long acc[8][4];
        #pragma unroll
        for (int i = 0; i < 8; ++i)
            #pragma unroll
            for (int j = 0; j < 4; ++j) acc[i][j] = 0ULL;

        const float* kb = &sh[OFF_K + p0 * KSTR];
        const float* mb = &sh[OFF_M + hb];
        #pragma unroll 4
        for (int d = 0; d < D; ++d) {
            unsigned long long kd[8];
            #pragma unroll
            for (int i = 0; i < 8; ++i) { float kv = kb[i * KSTR + d]; kd[i] = pk2(kv, kv); }
            float4 m0 = *(const float4*)(mb + d * MSTR);
            float4 m1 = *(const float4*)(mb + d * MSTR + 4);
            unsigned long long mp[4] = { pk2(m0.x, m0.y), pk2(m0.z, m0.w),
                                         pk2(m1.x, m1.y), pk2(m1.z, m1.w) };
            #pragma unroll
            for (int i = 0; i < 8; ++i)
                #pragma unroll
                for (int j = 0; j < 4; ++j) fma2(acc[i][j], kd[i], mp[j]);
        }
        #pragma unroll
        for (int i = 0; i < 8; ++i) {
            int t = p0 + i;
            #pragma unroll
            for (int j = 0; j < 4; ++j) {
                int h = hb + 2 * j;
                float x, y; upk2(acc[i][j], x, y);
                x += sh[OFF_B0 + h];     y += sh[OFF_B0 + h + 1];
                x = (x >= 0.f) ? x : x * sh[OFF_A0 + h];
                y = (y >= 0.f) ? y : y * sh[OFF_A0 + h + 1];
                sh[OFF_H0V + t * H0STR + h]     = x;
                sh[OFF_H0V + t * H0STR + h + 1] = y;
            }
        }
    }
    __syncthreads();

    // ------- GEMM2: H1 = H0 @ W1 (fused bias+PReLU), then dot with Wo -> logits (smem atomics) ---
    // 250 tiles of 4 pos x 8 g
    if (tid < 250) {
        const int gg = tid % 5, pg = tid / 5;
        const int p0 = pg * 4, gb = gg * 8;
        unsigned long long acc[4][4];
        #pragma unroll
        for (int i = 0; i < 4; ++i)
            #pragma unroll
            for (int j = 0; j < 4; ++j) acc[i][j] = 0ULL;

        const float* hb0 = &sh[OFF_H0V + p0 * H0STR];
        const float* wb  = &sh[OFF_W1 + gb];
        #pragma unroll 4
        for (int h = 0; h < H0; ++h) {
            unsigned long long hd[4];
            #pragma unroll
            for (int i = 0; i < 4; ++i) { float hv = hb0[i * H0STR + h]; hd[i] = pk2(hv, hv); }
            float4 w0 = *(const float4*)(wb + h * H1);
            float4 w1 = *(const float4*)(wb + h * H1 + 4);
            unsigned long long wp[4] = { pk2(w0.x, w0.y), pk2(w0.z, w0.w),
                                         pk2(w1.x, w1.y), pk2(w1.z, w1.w) };
            #pragma unroll
            for (int i = 0; i < 4; ++i)
                #pragma unroll
                for (int j = 0; j < 4; ++j) fma2(acc[i][j], hd[i], wp[j]);
        }
        #pragma unroll
        for (int i = 0; i < 4; ++i) {
            float part = 0.0f;
            #pragma unroll
            for (int j = 0; j < 4; ++j) {
                int g = gb + 2 * j;
                float x, y; upk2(acc[i][j], x, y);
                x += sh[OFF_B1 + g];     y += sh[OFF_B1 + g + 1];
                x = (x >= 0.f) ? x : x * sh[OFF_A1 + g];
                y = (y >= 0.f) ? y : y * sh[OFF_A1 + g + 1];
                part += x * sh[OFF_WO + g] + y * sh[OFF_WO + g + 1];
            }
            atomicAdd(&sh[OFF_LOG + p0 + i], part);
        }
    }
    __syncthreads();

    // ---------------- Softmax over T with mask (exact, max-subtracted) ----------------
    {
        const int t = tid;
        float l = -3.402823466e38f;
        if (t < T) {
            float lv = sh[OFF_LOG + t] + sh[OFF_BO];
            if (mask[(size_t)b * T + t] == 0) lv = NEG_INF_F;
            sh[OFF_LOG + t] = lv;
            l = lv;
        }
        #pragma unroll
        for (int o = 16; o > 0; o >>= 1) l = fmaxf(l, __shfl_xor_sync(0xffffffffu, l, o));
        if ((tid & 31) == 0) sh[OFF_RED + (tid >> 5)] = l;
        __syncthreads();
        float mx = sh[OFF_RED];
        #pragma unroll
        for (int w = 1; w < 8; ++w) mx = fmaxf(mx, sh[OFF_RED + w]);
        __syncthreads();  // everyone has mx; safe to reuse OFF_RED

        float e = 0.0f;
        if (t < T) e = expf(sh[OFF_LOG + t] - mx);
        float s = e;
        #pragma unroll
        for (int o = 16; o > 0; o >>= 1) s += __shfl_xor_sync(0xffffffffu, s, o);
        if ((tid & 31) == 0) sh[OFF_RED + (tid >> 5)] = s;
        __syncthreads();
        float tot = 0.0f;
        #pragma unroll
        for (int w = 0; w < 8; ++w) tot += sh[OFF_RED + w];
        if (t < T) sh[OFF_LOG + t] = e / tot;
        __syncthreads();
    }

    // ---------------- Output: out[b][d] = sum_t w[t] * v[b][t][d] ----------------
    {
        const int dcol = tid & 63, part = tid >> 6;   // 64 cols x 4 partitions
        const float* vb = v + (size_t)b * T * D;
        float acc = 0.0f;
        const int t0 = part * 50;
        #pragma unroll 5
        for (int t = t0; t < t0 + 50; ++t)
            acc += sh[OFF_LOG + t] * vb[(size_t)t * D + dcol];
        sh[OFF_M + tid] = acc;   // reuse M region as 256-float scratch
        __syncthreads();
        if (tid < 64)
            out[(size_t)b * D + tid] = sh[OFF_M + tid] + sh[OFF_M + 64 + tid]
                                     + sh[OFF_M + 128 + tid] + sh[OFF_M + 192 + tid];
    }
}

extern "C" void kernel_launch(void* const* d_in, const int* in_sizes, int n_in,
                              void* d_out, int out_size) {
    const float* q   = (const float*)d_in[0];
    const float* k   = (const float*)d_in[1];
    const float* v   = (const float*)d_in[2];
    const float* W0  = (const float*)d_in[3];
    const float* b0  = (const float*)d_in[4];
    const float* a0  = (const float*)d_in[5];
    const float* W1  = (const float*)d_in[6];
    const float* b1  = (const float*)d_in[7];
    const float* a1  = (const float*)d_in[8];
    const float* Wo  = (const float*)d_in[9];
    const float* bo  = (const float*)d_in[10];
    const int*   mask= (const int*)d_in[11];
    float* out = (float*)d_out;

    const int B = in_sizes[0] / D;
    const size_t smem = (size_t)SMEM_FLOATS * sizeof(float);
    cudaFuncSetAttribute(attn_din_kernel, cudaFuncAttributeMaxDynamicSharedMemorySize, (int)smem);

    attn_din_kernel<<<B, 256, smem>>>(q, k, v, W0, b0, a0, W1, b1, a1, Wo, bo, mask, out);
}

// round 17
// speedup vs baseline: 1.0005x; 1.0005x over previous
#include <cuda_runtime.h>
#include <cstdint>

// Problem constants (fixed shapes per reference setup_inputs)
constexpr int D  = 64;    // feature dim
constexpr int T  = 200;   // sequence length
constexpr int H0 = 80;    // hidden 0
constexpr int H1 = 40;    // hidden 1

constexpr float NEG_INF_F = -4294967295.0f;

// Shared-memory layout (in floats)
constexpr int KSTR  = 65;   // K tile row stride (odd -> conflict-free column reads)
constexpr int MSTR  = 80;   // M matrix row stride (16B-aligned rows for LDS.128)
constexpr int H0STR = 81;   // H0 tile row stride

constexpr int OFF_Q   = 0;
constexpr int OFF_M   = 64;                       // 64 x 80
constexpr int OFF_B0  = OFF_M  + D * MSTR;        // 5184
constexpr int OFF_W1  = OFF_B0 + H0;              // 5264 (80x40, rows 16B aligned)
constexpr int OFF_B1  = OFF_W1 + H0 * H1;         // 8464
constexpr int OFF_A0  = OFF_B1 + H1;              // 8504
constexpr int OFF_A1  = OFF_A0 + H0;              // 8584
constexpr int OFF_WO  = OFF_A1 + H1;              // 8624
constexpr int OFF_BO  = OFF_WO + H1;              // 8664
constexpr int OFF_RED = 8668;                     // 8 floats (warp partials)
constexpr int OFF_LOG = OFF_RED + 8;              // 8676, 200 floats
constexpr int OFF_K   = 8880;                     // 200 x 65
constexpr int OFF_H0V = OFF_K + T * KSTR;         // 21880, 200 x 81
constexpr int SMEM_FLOATS = OFF_H0V + T * H0STR;  // 38080 floats = 152320 B

// ---- packed f32x2 helpers (FFMA2 path on sm_103a) ----
__device__ __forceinline__ unsigned long long pk2(float lo, float hi) {
    unsigned long long r;
    asm("mov.b64 %0, {%1,%2};" : "=l"(r) : "f"(lo), "f"(hi));
    return r;
}
__device__ __forceinline__ void upk2(unsigned long long v, float& a, float& b) {
    asm("mov.b64 {%0,%1}, %2;" : "=f"(a), "=f"(b) : "l"(v));
}
__device__ __forceinline__ void fma2(unsigned long long& d, unsigned long long a, unsigned long long b) {
    asm("fma.rn.f32x2 %0, %1, %2, %0;" : "+l"(d) : "l"(a), "l"(b));
}

__global__ void __launch_bounds__(256, 1)
attn_din_kernel(const float* __restrict__ q,  const float* __restrict__ k,
                const float* __restrict__ v,  const float* __restrict__ W0,
                const float* __restrict__ b0, const float* __restrict__ a0,
                const float* __restrict__ W1, const float* __restrict__ b1,
                const float* __restrict__ a1, const float* __restrict__ Wo,
                const float* __restrict__ bo, const int* __restrict__ mask,
                float* __restrict__ out)
{
    extern __shared__ float sh[];
    const int tid = threadIdx.x;
    const int b   = blockIdx.x;

    // ---------------- Phase A: stage q + small params, init logits ----------------
    if (tid < D)  sh[OFF_Q + tid] = q[(size_t)b * D + tid];
    for (int i = tid; i < H0 * H1; i += 256) sh[OFF_W1 + i] = W1[i];
    if (tid < H1) { sh[OFF_B1 + tid] = b1[tid]; sh[OFF_A1 + tid] = a1[tid]; sh[OFF_WO + tid] = Wo[tid]; }
    if (tid < H0) sh[OFF_A0 + tid] = a0[tid];
    if (tid == 0) sh[OFF_BO] = bo[0];
    if (tid < T)  sh[OFF_LOG + tid] = 0.0f;
    __syncthreads();  // sQ ready

    // ---------------- Phase B: fold q into layer-0: M_b and bias_b; stage K tile ----------------
    // M[d][h] = W0[64+d][h] - W0[128+d][h] + q[d] * W0[192+d][h]
    for (int e = tid; e < D * H0; e += 256) {
        int d = e / H0, h = e - d * H0;
        sh[OFF_M + d * MSTR + h] =
            W0[(64 + d) * H0 + h] - W0[(128 + d) * H0 + h] + sh[OFF_Q + d] * W0[(192 + d) * H0 + h];
    }
    // bias0[h] = b0[h] + sum_d q[d]*(W0[d][h] + W0[128+d][h])
    if (tid < H0) {
        float s = b0[tid];
        #pragma unroll 4
        for (int d = 0; d < D; ++d)
            s += sh[OFF_Q + d] * (W0[d * H0 + tid] + W0[(128 + d) * H0 + tid]);
        sh[OFF_B0 + tid] = s;
    }
    // K tile: [t][d] with stride KSTR
    {
        const float4* kg = (const float4*)(k + (size_t)b * T * D);
        for (int i = tid; i < T * D / 4; i += 256) {
            int t = i / (D / 4), c = i - t * (D / 4);
            float4 vv = kg[i];
            float* dst = &sh[OFF_K + t * KSTR + c * 4];
            dst[0] = vv.x; dst[1] = vv.y; dst[2] = vv.z; dst[3] = vv.w;
        }
    }
    __syncthreads();

    // ---------------- GEMM1: H0[200][80] = K[200][64] @ M[64][80], fused bias+PReLU --------------
    // 250 tiles of 8 pos x 8 h; output-feature pairs packed in f32x2 (weights via LDS.128 pairs)
    if (tid < 250) {
        const int hg = tid % 10, pg = tid / 10;
        const int p0 = pg * 8, hb = hg * 8;
        unsigned long long acc[8][4];
        #pragma unroll
        for (int i = 0; i < 8; ++i)
            #pragma unroll
            for (int j = 0; j < 4; ++j) acc[i][j] = 0ULL;

        const float* kb = &sh[OFF_K + p0 * KSTR];
        const float* mb = &sh[OFF_M + hb];
        #pragma unroll 4
        for (int d = 0; d < D; ++d) {
            unsigned long long kd[8];
            #pragma unroll
            for (int i = 0; i < 8; ++i) { float kv = kb[i * KSTR + d]; kd[i] = pk2(kv, kv); }
            float4 m0 = *(const float4*)(mb + d * MSTR);
            float4 m1 = *(const float4*)(mb + d * MSTR + 4);
            unsigned long long mp[4] = { pk2(m0.x, m0.y), pk2(m0.z, m0.w),
                                         pk2(m1.x, m1.y), pk2(m1.z, m1.w) };
            #pragma unroll
            for (int i = 0; i < 8; ++i)
                #pragma unroll
                for (int j = 0; j < 4; ++j) fma2(acc[i][j], kd[i], mp[j]);
        }
        #pragma unroll
        for (int i = 0; i < 8; ++i) {
            int t = p0 + i;
            #pragma unroll
            for (int j = 0; j < 4; ++j) {
                int h = hb + 2 * j;
                float x, y; upk2(acc[i][j], x, y);
                x += sh[OFF_B0 + h];     y += sh[OFF_B0 + h + 1];
                x = (x >= 0.f) ? x : x * sh[OFF_A0 + h];
                y = (y >= 0.f) ? y : y * sh[OFF_A0 + h + 1];
                sh[OFF_H0V + t * H0STR + h]     = x;
                sh[OFF_H0V + t * H0STR + h + 1] = y;
            }
        }
    }
    __syncthreads();

    // ------- GEMM2: H1 = H0 @ W1 (fused bias+PReLU), then dot with Wo -> logits (smem atomics) ---
    // 250 tiles of 4 pos x 8 g
    if (tid < 250) {
        const int gg = tid % 5, pg = tid / 5;
        const int p0 = pg * 4, gb = gg * 8;
        unsigned long long acc[4][4];
        #pragma unroll
        for (int i = 0; i < 4; ++i)
            #pragma unroll
            for (int j = 0; j < 4; ++j) acc[i][j] = 0ULL;

        const float* hb0 = &sh[OFF_H0V + p0 * H0STR];
        const float* wb  = &sh[OFF_W1 + gb];
        #pragma unroll 4
        for (int h = 0; h < H0; ++h) {
            unsigned long long hd[4];
            #pragma unroll
            for (int i = 0; i < 4; ++i) { float hv = hb0[i * H0STR + h]; hd[i] = pk2(hv, hv); }
            float4 w0 = *(const float4*)(wb + h * H1);
            float4 w1 = *(const float4*)(wb + h * H1 + 4);
            unsigned long long wp[4] = { pk2(w0.x, w0.y), pk2(w0.z, w0.w),
                                         pk2(w1.x, w1.y), pk2(w1.z, w1.w) };
            #pragma unroll
            for (int i = 0; i < 4; ++i)
                #pragma unroll
                for (int j = 0; j < 4; ++j) fma2(acc[i][j], hd[i], wp[j]);
        }
        #pragma unroll
        for (int i = 0; i < 4; ++i) {
            float part = 0.0f;
            #pragma unroll
            for (int j = 0; j < 4; ++j) {
                int g = gb + 2 * j;
                float x, y; upk2(acc[i][j], x, y);
                x += sh[OFF_B1 + g];     y += sh[OFF_B1 + g + 1];
                x = (x >= 0.f) ? x : x * sh[OFF_A1 + g];
                y = (y >= 0.f) ? y : y * sh[OFF_A1 + g + 1];
                part += x * sh[OFF_WO + g] + y * sh[OFF_WO + g + 1];
            }
            atomicAdd(&sh[OFF_LOG + p0 + i], part);
        }
    }
    __syncthreads();

    // ---------------- Softmax over T with mask (exact, max-subtracted) ----------------
    {
        const int t = tid;
        float l = -3.402823466e38f;
        if (t < T) {
            float lv = sh[OFF_LOG + t] + sh[OFF_BO];
            if (mask[(size_t)b * T + t] == 0) lv = NEG_INF_F;
            sh[OFF_LOG + t] = lv;
            l = lv;
        }
        #pragma unroll
        for (int o = 16; o > 0; o >>= 1) l = fmaxf(l, __shfl_xor_sync(0xffffffffu, l, o));
        if ((tid & 31) == 0) sh[OFF_RED + (tid >> 5)] = l;
        __syncthreads();
        float mx = sh[OFF_RED];
        #pragma unroll
        for (int w = 1; w < 8; ++w) mx = fmaxf(mx, sh[OFF_RED + w]);
        __syncthreads();  // everyone has mx; safe to reuse OFF_RED

        float e = 0.0f;
        if (t < T) e = expf(sh[OFF_LOG + t] - mx);
        float s = e;
        #pragma unroll
        for (int o = 16; o > 0; o >>= 1) s += __shfl_xor_sync(0xffffffffu, s, o);
        if ((tid & 31) == 0) sh[OFF_RED + (tid >> 5)] = s;
        __syncthreads();
        float tot = 0.0f;
        #pragma unroll
        for (int w = 0; w < 8; ++w) tot += sh[OFF_RED + w];
        if (t < T) sh[OFF_LOG + t] = e / tot;
        __syncthreads();
    }

    // ---------------- Output: out[b][d] = sum_t w[t] * v[b][t][d] ----------------
    {
        const int dcol = tid & 63, part = tid >> 6;   // 64 cols x 4 partitions
        const float* vb = v + (size_t)b * T * D;
        float acc = 0.0f;
        const int t0 = part * 50;
        #pragma unroll 5
        for (int t = t0; t < t0 + 50; ++t)
            acc += sh[OFF_LOG + t] * vb[(size_t)t * D + dcol];
        sh[OFF_M + tid] = acc;   // reuse M region as 256-float scratch
        __syncthreads();
        if (tid < 64)
            out[(size_t)b * D + tid] = sh[OFF_M + tid] + sh[OFF_M + 64 + tid]
                                     + sh[OFF_M + 128 + tid] + sh[OFF_M + 192 + tid];
    }
}

extern "C" void kernel_launch(void* const* d_in, const int* in_sizes, int n_in,
                              void* d_out, int out_size) {
    const float* q   = (const float*)d_in[0];
    const float* k   = (const float*)d_in[1];
    const float* v   = (const float*)d_in[2];
    const float* W0  = (const float*)d_in[3];
    const float* b0  = (const float*)d_in[4];
    const float* a0  = (const float*)d_in[5];
    const float* W1  = (const float*)d_in[6];
    const float* b1  = (const float*)d_in[7];
    const float* a1  = (const float*)d_in[8];
    const float* Wo  = (const float*)d_in[9];
    const float* bo  = (const float*)d_in[10];
    const int*   mask= (const int*)d_in[11];
    float* out = (float*)d_out;

    const int B = in_sizes[0] / D;
    const size_t smem = (size_t)SMEM_FLOATS * sizeof(float);
    cudaFuncSetAttribute(attn_din_kernel, cudaFuncAttributeMaxDynamicSharedMemorySize, (int)smem);

    attn_din_kernel<<<B, 256, smem>>>(q, k, v, W0, b0, a0, W1, b1, a1, Wo, bo, mask, out);
}